// round 14
// baseline (speedup 1.0000x reference)
#include <cuda_runtime.h>
#include <math.h>

#define BB 32
#define SS 512
#define DD 512
#define HH 8
#define DF 64

// ---------------- scratch (no allocation allowed) ----------------
__device__ float g_qh[BB * SS * DD];
__device__ float g_kh[BB * SS * DD];
__device__ float g_vh[BB * SS * DD];
__device__ float g_vt[BB * SS * DD];   // V^T per batch: [b][h*64+d][s]
__device__ float g_at[BB * SS * DD];
__device__ float g_diff[BB * SS * SS];
__device__ float g_qr[BB * SS * DD];
__device__ float g_kr[BB * SS * DD];
__device__ float g_vr[BB * SS * DD];
__device__ float g_wk[DD * DD];
__device__ float g_wv[DD * DD];
__device__ float g_wo[DD * DD];

// ---------------- tf32 helpers ----------------
__device__ __forceinline__ unsigned f2tf(float x) {
    unsigned r;
    asm("cvt.rna.tf32.f32 %0, %1;" : "=r"(r) : "f"(x));
    return r;
}

__device__ __forceinline__ void mma_tf32(float c[4], const unsigned a[4],
                                         unsigned b0, unsigned b1) {
    asm volatile(
        "mma.sync.aligned.m16n8k8.row.col.f32.tf32.tf32.f32 "
        "{%0,%1,%2,%3}, {%4,%5,%6,%7}, {%8,%9}, {%0,%1,%2,%3};\n"
        : "+f"(c[0]), "+f"(c[1]), "+f"(c[2]), "+f"(c[3])
        : "r"(a[0]), "r"(a[1]), "r"(a[2]), "r"(a[3]), "r"(b0), "r"(b1));
}

__device__ __forceinline__ void cp_async16(unsigned smem, const void* g) {
    asm volatile("cp.async.cg.shared.global [%0], [%1], 16;\n" :: "r"(smem), "l"(g));
}

// ---------------- diff precompute (causal triangle only) ----------------
__global__ __launch_bounds__(128) void diff_kernel(const float* __restrict__ qde,
                                                   float* __restrict__ out)
{
    const int i = blockIdx.x, b = blockIdx.y, t = threadIdx.x;
    if (t * 4 > i) return;
    size_t off = ((size_t)b * SS + i) * SS + t * 4;
    float4 x = *(const float4*)(qde + off);
    float4 o;
    o.x = __expf(1.f / (1.f + __expf(-x.x)));
    o.y = __expf(1.f / (1.f + __expf(-x.y)));
    o.z = __expf(1.f / (1.f + __expf(-x.z)));
    o.w = __expf(1.f / (1.f + __expf(-x.w)));
    *(float4*)(out + off) = o;
}

// ---------------- merged tf32 pre-round ----------------
__global__ __launch_bounds__(256) void round_all(
    const float* __restrict__ q, const float* __restrict__ k, const float* __restrict__ v,
    const float* __restrict__ Wk, const float* __restrict__ Wv, const float* __restrict__ Wo,
    float* __restrict__ qr, float* __restrict__ kr, float* __restrict__ vr,
    float* __restrict__ wk, float* __restrict__ wv, float* __restrict__ wo)
{
    const int bx = blockIdx.x;
    const float* s; float* d; int i;
    if (bx < 8192)        { s = q;  d = qr; i = bx * 256 + threadIdx.x; }
    else if (bx < 16384)  { s = k;  d = kr; i = (bx - 8192) * 256 + threadIdx.x; }
    else if (bx < 24576)  { s = v;  d = vr; i = (bx - 16384) * 256 + threadIdx.x; }
    else {
        int w = (bx - 24576) * 256 + threadIdx.x;
        if (w < 65536)       { s = Wk; d = wk; i = w; }
        else if (w < 131072) { s = Wv; d = wv; i = w - 65536; }
        else                 { s = Wo; d = wo; i = w - 131072; }
    }
    float4 x = ((const float4*)s)[i];
    uint4 o = {f2tf(x.x), f2tf(x.y), f2tf(x.z), f2tf(x.w)};
    ((uint4*)d)[i] = o;
}

// ---------------- V transpose: vh [b][s][hd] -> vt [b][hd][s] ----------------
__global__ __launch_bounds__(256) void transpose_v(const float* __restrict__ vh,
                                                   float* __restrict__ vt)
{
    __shared__ float t[32][33];
    const int b = blockIdx.z;
    const int s0 = blockIdx.x * 32, d0 = blockIdx.y * 32;
    const int tx = threadIdx.x & 31, ty = threadIdx.x >> 5;
#pragma unroll
    for (int i = 0; i < 32; i += 8)
        t[ty + i][tx] = vh[((size_t)b * SS + s0 + ty + i) * DD + d0 + tx];
    __syncthreads();
#pragma unroll
    for (int i = 0; i < 32; i += 8)
        vt[((size_t)b * DD + d0 + ty + i) * SS + s0 + tx] = t[tx][ty + i];
}

// ---------------- pipelined tf32 GEMM: C = X @ W^T + bias ----------------
#define TG_SMEM_BYTES 61440
#define NIT 32

__global__ __launch_bounds__(256, 2) void tgemm3(
    const float* __restrict__ X0, const float* __restrict__ X1, const float* __restrict__ X2,
    const float* __restrict__ W0, const float* __restrict__ W1, const float* __restrict__ W2,
    const float* __restrict__ B0, const float* __restrict__ B1, const float* __restrict__ B2,
    float* __restrict__ C0, float* __restrict__ C1, float* __restrict__ C2,
    int roundMask)
{
    extern __shared__ float smem[];
    unsigned* smem_u = (unsigned*)smem;

    const int z = blockIdx.z;
    const float* X = (z == 0) ? X0 : (z == 1) ? X1 : X2;
    const float* W = (z == 0) ? W0 : (z == 1) ? W1 : W2;
    const float* bias = (z == 0) ? B0 : (z == 1) ? B1 : B2;
    float* C = (z == 0) ? C0 : (z == 1) ? C1 : C2;
    const bool rnd = (roundMask >> z) & 1;

    const int tid = threadIdx.x;
    const int lane = tid & 31;
    const int warp = tid >> 5;
    const int m0 = blockIdx.y * 128;
    const int n0 = blockIdx.x * 128;
    const int wm = (warp & 3) * 32;
    const int wn = (warp >> 2) * 64;
    const int g4 = lane >> 2;
    const int t4 = lane & 3;

    float c[2][8][4];
#pragma unroll
    for (int mf = 0; mf < 2; mf++)
#pragma unroll
        for (int nf = 0; nf < 8; nf++)
#pragma unroll
            for (int j = 0; j < 4; j++) c[mf][nf][j] = 0.f;

    const unsigned smem_base = (unsigned)__cvta_generic_to_shared(smem);

#define PREFETCH(st, k0)                                                         \
    {                                                                            \
        const unsigned sb = smem_base + (st) * 5120 * 4;                         \
        _Pragma("unroll")                                                        \
        for (int gch = 0; gch < 2; gch++) {                                      \
            int ch = tid + gch * 256;                                            \
            int row = ch >> 2, c4 = ch & 3;                                      \
            cp_async16(sb + (row * 20 + c4 * 4) * 4,                             \
                       X + (size_t)(m0 + row) * 512 + (k0) + c4 * 4);            \
            cp_async16(sb + (2560 + row * 20 + c4 * 4) * 4,                      \
                       W + (size_t)(n0 + row) * 512 + (k0) + c4 * 4);            \
        }                                                                        \
    }

    PREFETCH(0, 0);
    asm volatile("cp.async.commit_group;\n");
    PREFETCH(1, 16);
    asm volatile("cp.async.commit_group;\n");

    for (int it = 0; it < NIT; it++) {
        asm volatile("cp.async.wait_group 1;\n");
        __syncthreads();

        const int pf = it + 2;
        if (pf < NIT) { PREFETCH(pf % 3, pf * 16); }
        asm volatile("cp.async.commit_group;\n");

        const unsigned* As = smem_u + (it % 3) * 5120;
        const unsigned* Ws = As + 2560;

#pragma unroll
        for (int kk = 0; kk < 16; kk += 8) {
            const int kc = kk + t4;
            unsigned a[2][4], bf[8][2];
#pragma unroll
            for (int mf = 0; mf < 2; mf++) {
                const int ar = wm + mf * 16 + g4;
                a[mf][0] = As[ar * 20 + kc];
                a[mf][1] = As[(ar + 8) * 20 + kc];
                a[mf][2] = As[ar * 20 + kc + 4];
                a[mf][3] = As[(ar + 8) * 20 + kc + 4];
            }
#pragma unroll
            for (int nf = 0; nf < 8; nf++) {
                const int br = wn + nf * 8 + g4;
                bf[nf][0] = Ws[br * 20 + kc];
                bf[nf][1] = Ws[br * 20 + kc + 4];
            }
#pragma unroll
            for (int mf = 0; mf < 2; mf++)
#pragma unroll
                for (int nf = 0; nf < 8; nf++)
                    mma_tf32(c[mf][nf], a[mf], bf[nf][0], bf[nf][1]);
        }
        __syncthreads();
    }

#pragma unroll
    for (int mf = 0; mf < 2; mf++) {
#pragma unroll
        for (int nf = 0; nf < 8; nf++) {
            const int row = m0 + wm + mf * 16 + g4;
            const int col = n0 + wn + nf * 8 + t4 * 2;
            const float b0v = bias[col], b1v = bias[col + 1];
            float v00 = c[mf][nf][0] + b0v, v01 = c[mf][nf][1] + b1v;
            float v10 = c[mf][nf][2] + b0v, v11 = c[mf][nf][3] + b1v;
            if (rnd) {
                v00 = __uint_as_float(f2tf(v00)); v01 = __uint_as_float(f2tf(v01));
                v10 = __uint_as_float(f2tf(v10)); v11 = __uint_as_float(f2tf(v11));
            }
            float2 o0 = {v00, v01}, o1 = {v10, v11};
            *(float2*)(C + (size_t)row * 512 + col) = o0;
            *(float2*)(C + (size_t)(row + 8) * 512 + col) = o1;
        }
    }
}

// ---------------- fused AKT attention v11 (64-row blocks, 512 thr, cp.async pipeline) ----------------
// SMEM words: stage0 0..4352 | stage1 4352..8704 | buf 8704..41728 (64x516)
//             inv2 41728..41792 | qhi 41792..46144 | qlo 46144..50496
#define ATH5 512
#define BSTR 516
#define ATTN11_SMEM_BYTES (50496 * 4)

__global__ __launch_bounds__(512, 1) void attn11_kernel(
    const float* __restrict__ qh, const float* __restrict__ kh,
    const float* __restrict__ vt, const float* __restrict__ diffm,
    const float* __restrict__ gammas, const int* __restrict__ zp,
    float* __restrict__ attn)
{
    extern __shared__ float sm[];
    unsigned* buf0_u = (unsigned*)sm;
    unsigned* buf1_u = (unsigned*)(sm + 4352);
    float* buf   = sm + 8704;
    float* inv2  = sm + 41728;
    unsigned* qhi_u = (unsigned*)(sm + 41792);
    unsigned* qlo_u = (unsigned*)(sm + 46144);
    unsigned* buf_u = (unsigned*)buf;

    const int tid = threadIdx.x;
    const int lane = tid & 31, warp = tid >> 5;
    const int b = blockIdx.z, h = blockIdx.y;
    const int i0 = blockIdx.x * 64;
    const int nchunk = blockIdx.x + 1;           // (i0+64)/64
    const int kmax_pad = nchunk * 64;

    const unsigned* khb_u = (const unsigned*)(kh + (size_t)b * SS * DD + h * DF);
    const float*    qhb   = qh + (size_t)b * SS * DD + h * DF;
    const unsigned* vtb_u = (const unsigned*)(vt + ((size_t)b * DD + h * DF) * SS);
    const float*    dfb   = diffm + (size_t)b * SS * SS;

    const unsigned smem_b = (unsigned)__cvta_generic_to_shared(sm);

    // K chunk staging: 64 rows x 16 uint4; thread does 2 cp.async
#define STAGE_K(kc, dstw)                                                        \
    {                                                                            \
        _Pragma("unroll")                                                        \
        for (int gg = 0; gg < 2; gg++) {                                         \
            int li = tid + gg * 512;                                             \
            int kr = li >> 4, d4 = (li & 15) << 2;                               \
            cp_async16(smem_b + ((dstw) + kr * 68 + d4) * 4,                     \
                       khb_u + (size_t)((kc) * 64 + kr) * DD + d4);              \
        }                                                                        \
    }
#define STAGE_V(kc, dstw)                                                        \
    {                                                                            \
        _Pragma("unroll")                                                        \
        for (int gg = 0; gg < 2; gg++) {                                         \
            int li = tid + gg * 512;                                             \
            int dd = li >> 4, k4 = (li & 15) << 2;                               \
            cp_async16(smem_b + ((dstw) + dd * 68 + k4) * 4,                     \
                       vtb_u + (size_t)dd * SS + (kc) * 64 + k4);                \
        }                                                                        \
    }

    // prefetch K chunks 0 and 1 immediately (hidden under phase 0)
    STAGE_K(0, 0u);
    asm volatile("cp.async.commit_group;\n");
    if (nchunk > 1) STAGE_K(1, 4352u);
    asm volatile("cp.async.commit_group;\n");

    const float g = gammas[h];
    const float gamma_h = -(fmaxf(g, 0.f) + log1pf(__expf(-fabsf(g))));
    const int zpv = zp[0];

    const int g4 = lane >> 2, t4 = lane & 3;
    const int mh = warp & 3;          // 4 m-halves of 16 rows -> 64 rows
    const int ng = warp >> 2;         // 0..3, covers nt = 2*ng, 2*ng+1
    const int arow = mh * 16 + g4;    // 0..63

    // ---- phase 0: load 64 Q rows, scale 0.125, split hi/lo tf32 ----
#pragma unroll
    for (int gg = 0; gg < 2; gg++) {
        int li = tid + gg * 512;
        int r = li >> 4, d4 = (li & 15) << 2;
        float4 v = *(const float4*)(qhb + (size_t)(i0 + r) * DD + d4);
        v.x *= 0.125f; v.y *= 0.125f; v.z *= 0.125f; v.w *= 0.125f;
        unsigned hx = f2tf(v.x), hy = f2tf(v.y), hz = f2tf(v.z), hw = f2tf(v.w);
        uint4 hv = {hx, hy, hz, hw};
        uint4 lv;
        lv.x = f2tf(v.x - __uint_as_float(hx));
        lv.y = f2tf(v.y - __uint_as_float(hy));
        lv.z = f2tf(v.z - __uint_as_float(hz));
        lv.w = f2tf(v.w - __uint_as_float(hw));
        *(uint4*)(qhi_u + r * 68 + d4) = hv;
        *(uint4*)(qlo_u + r * 68 + d4) = lv;
    }
    __syncthreads();

    unsigned ahi[8][4], alo[8][4];
#pragma unroll
    for (int ks = 0; ks < 8; ks++) {
        int base = arow * 68 + ks * 8 + t4;
        ahi[ks][0] = qhi_u[base];
        ahi[ks][1] = qhi_u[base + 8 * 68];
        ahi[ks][2] = qhi_u[base + 4];
        ahi[ks][3] = qhi_u[base + 8 * 68 + 4];
        alo[ks][0] = qlo_u[base];
        alo[ks][1] = qlo_u[base + 8 * 68];
        alo[ks][2] = qlo_u[base + 4];
        alo[ks][3] = qlo_u[base + 8 * 68 + 4];
    }

    // ---- phase 1: S = (Q/8) K^T, double-buffered ----
    for (int kc = 0; kc < nchunk; kc++) {
        asm volatile("cp.async.wait_group 1;\n");
        __syncthreads();
        const unsigned* st = (kc & 1) ? buf1_u : buf0_u;

#pragma unroll
        for (int sub = 0; sub < 2; sub++) {
            const int nt = 2 * ng + sub;
            if (kc * 64 + nt * 8 <= i0 + 63) {
                float c[4] = {0.f, 0.f, 0.f, 0.f};
#pragma unroll
                for (int ks = 0; ks < 8; ks++) {
                    unsigned b0 = st[(nt * 8 + g4) * 68 + ks * 8 + t4];
                    unsigned b1 = st[(nt * 8 + g4) * 68 + ks * 8 + t4 + 4];
                    mma_tf32(c, ahi[ks], b0, b1);
                    mma_tf32(c, alo[ks], b0, b1);
                }
                const int col = kc * 64 + nt * 8 + t4 * 2;
                float2 v0 = {c[0], c[1]}, v1 = {c[2], c[3]};
                *(float2*)(buf + arow * BSTR + col) = v0;
                *(float2*)(buf + (arow + 8) * BSTR + col) = v1;
            }
        }
        __syncthreads();

        const int pf = kc + 2;
        if (pf < nchunk) {
            if (pf & 1) { STAGE_K(pf, 4352u); } else { STAGE_K(pf, 0u); }
        }
        asm volatile("cp.async.commit_group;\n");
    }

    // prefetch V chunks 0 and 1 — land during phase 2
    STAGE_V(0, 0u);
    asm volatile("cp.async.commit_group;\n");
    if (nchunk > 1) STAGE_V(1, 4352u);
    asm volatile("cp.async.commit_group;\n");

    // ---- phase 2: softmax1 -> cumsum -> decay -> softmax2 ----
    for (int rr = 0; rr < 4; rr++) {
        const int r = warp + rr * 16;
        const int i = i0 + r;
        float* row = buf + r * BSTR;
        unsigned* row_u = buf_u + r * BSTR;
        const float* drow = dfb + (size_t)i * SS;
        const int kb = lane * 16;
        const bool act = kb < kmax_pad;

        float s[16], dfv[16];
        if (act) {
#pragma unroll
            for (int j4 = 0; j4 < 4; j4++) {
                float4 v = *(float4*)(row + kb + j4 * 4);
                s[j4 * 4 + 0] = v.x; s[j4 * 4 + 1] = v.y;
                s[j4 * 4 + 2] = v.z; s[j4 * 4 + 3] = v.w;
                float4 dv = *(const float4*)(drow + kb + j4 * 4);
                dfv[j4 * 4 + 0] = dv.x; dfv[j4 * 4 + 1] = dv.y;
                dfv[j4 * 4 + 2] = dv.z; dfv[j4 * 4 + 3] = dv.w;
            }
        }

        float m1 = -1e32f;
#pragma unroll
        for (int j = 0; j < 16; j++)
            if (act && kb + j <= i) m1 = fmaxf(m1, s[j]);
#pragma unroll
        for (int o = 16; o > 0; o >>= 1) m1 = fmaxf(m1, __shfl_xor_sync(0xffffffffu, m1, o));

        float e[16];
        float run = 0.f;
#pragma unroll
        for (int j = 0; j < 16; j++) {
            e[j] = (act && kb + j <= i) ? __expf(s[j] - m1) : 0.f;
            run += e[j];
        }
        float tsc = run;
#pragma unroll
        for (int o = 1; o < 32; o <<= 1) {
            float u = __shfl_up_sync(0xffffffffu, tsc, o);
            if (lane >= o) tsc += u;
        }
        const float sum1 = __shfl_sync(0xffffffffu, tsc, 31);
        float cdf = tsc - run;
        const float invs = 1.f / sum1;

        float m2 = -1e32f;
#pragma unroll
        for (int j = 0; j < 16; j++) {
            cdf += e[j];
            const int k = kb + j;
            if (act && k <= i) {
                float rem = (sum1 - cdf) * invs;
                float px = rem * (float)(i - k);
                float dist = (px > 1e-30f) ? px * rsqrtf(px) : 0.f;
                float te = __expf(dist * gamma_h * dfv[j]);
                te = fminf(fmaxf(te, 1e-5f), 1e5f);
                float s2 = s[j] * te;
                s[j] = s2;
                m2 = fmaxf(m2, s2);
            } else {
                s[j] = -1e32f;
            }
        }
#pragma unroll
        for (int o = 16; o > 0; o >>= 1) m2 = fmaxf(m2, __shfl_xor_sync(0xffffffffu, m2, o));

        float sum2 = 0.f;
#pragma unroll
        for (int j = 0; j < 16; j++) {
            float e2 = (act && kb + j <= i) ? __expf(s[j] - m2) : 0.f;
            sum2 += e2;
            s[j] = e2;
        }
#pragma unroll
        for (int o = 16; o > 0; o >>= 1) sum2 += __shfl_xor_sync(0xffffffffu, sum2, o);

        if (act) {
#pragma unroll
            for (int j4 = 0; j4 < 4; j4++) {
                uint4 v;
                v.x = f2tf(s[j4 * 4 + 0]); v.y = f2tf(s[j4 * 4 + 1]);
                v.z = f2tf(s[j4 * 4 + 2]); v.w = f2tf(s[j4 * 4 + 3]);
                *(uint4*)(row_u + kb + j4 * 4) = v;
            }
        }
        if (lane == 0) inv2[r] = (i == 0 && zpv) ? 0.f : 1.f / sum2;
    }
    __syncthreads();

    // ---- phase 3: O = P V, double-buffered V^T ----
    {
        float co[2][4];
#pragma unroll
        for (int sub = 0; sub < 2; sub++)
#pragma unroll
            for (int j = 0; j < 4; j++) co[sub][j] = 0.f;

        for (int kc = 0; kc < nchunk; kc++) {
            asm volatile("cp.async.wait_group 1;\n");
            __syncthreads();
            const unsigned* st = (kc & 1) ? buf1_u : buf0_u;

#pragma unroll
            for (int ks = 0; ks < 8; ks++) {
                const int ki = kc * 64 + ks * 8 + t4;
                unsigned a[4];
                a[0] = buf_u[arow * BSTR + ki];
                a[1] = buf_u[(arow + 8) * BSTR + ki];
                a[2] = buf_u[arow * BSTR + ki + 4];
                a[3] = buf_u[(arow + 8) * BSTR + ki + 4];
#pragma unroll
                for (int sub = 0; sub < 2; sub++) {
                    const int nt = 2 * ng + sub;
                    unsigned b0 = st[(nt * 8 + g4) * 68 + ks * 8 + t4];
                    unsigned b1 = st[(nt * 8 + g4) * 68 + ks * 8 + t4 + 4];
                    mma_tf32(co[sub], a, b0, b1);
                }
            }
            __syncthreads();

            const int pf = kc + 2;
            if (pf < nchunk) {
                if (pf & 1) { STAGE_V(pf, 4352u); } else { STAGE_V(pf, 0u); }
            }
            asm volatile("cp.async.commit_group;\n");
        }

        const float s0 = inv2[arow];
        const float s1 = inv2[arow + 8];
#pragma unroll
        for (int sub = 0; sub < 2; sub++) {
            const int nt = 2 * ng + sub;
            const int col = h * DF + nt * 8 + t4 * 2;
            float2 o0, o1;
            o0.x = __uint_as_float(f2tf(co[sub][0] * s0));
            o0.y = __uint_as_float(f2tf(co[sub][1] * s0));
            o1.x = __uint_as_float(f2tf(co[sub][2] * s1));
            o1.y = __uint_as_float(f2tf(co[sub][3] * s1));
            *(float2*)(attn + ((size_t)b * SS + i0 + arow) * DD + col) = o0;
            *(float2*)(attn + ((size_t)b * SS + i0 + arow + 8) * DD + col) = o1;
        }
    }
#undef STAGE_K
#undef STAGE_V
}

// ---------------- launch ----------------
extern "C" void kernel_launch(void* const* d_in, const int* in_sizes, int n_in,
                              void* d_out, int out_size)
{
    const float* q      = (const float*)d_in[0];
    const float* k      = (const float*)d_in[1];
    const float* v      = (const float*)d_in[2];
    const int*   zpad   = (const int*)d_in[4];
    const float* qde    = (const float*)d_in[5];
    const float* Wk     = (const float*)d_in[6];
    const float* bk     = (const float*)d_in[7];
    const float* Wv     = (const float*)d_in[8];
    const float* bv     = (const float*)d_in[9];
    const float* Wo     = (const float*)d_in[10];
    const float* bo     = (const float*)d_in[11];
    const float* gammas = (const float*)d_in[12];
    float* out = (float*)d_out;

    float *qh, *kh, *vh, *vt, *at, *df, *qr, *kr, *vr, *wk, *wv, *wo;
    cudaGetSymbolAddress((void**)&qh, g_qh);
    cudaGetSymbolAddress((void**)&kh, g_kh);
    cudaGetSymbolAddress((void**)&vh, g_vh);
    cudaGetSymbolAddress((void**)&vt, g_vt);
    cudaGetSymbolAddress((void**)&at, g_at);
    cudaGetSymbolAddress((void**)&df, g_diff);
    cudaGetSymbolAddress((void**)&qr, g_qr);
    cudaGetSymbolAddress((void**)&kr, g_kr);
    cudaGetSymbolAddress((void**)&vr, g_vr);
    cudaGetSymbolAddress((void**)&wk, g_wk);
    cudaGetSymbolAddress((void**)&wv, g_wv);
    cudaGetSymbolAddress((void**)&wo, g_wo);

    diff_kernel<<<dim3(SS, BB), 128>>>(qde, df);                     // 1
    round_all<<<25344, 256>>>(q, k, v, Wk, Wv, Wo,
                              qr, kr, vr, wk, wv, wo);               // 2

    cudaFuncSetAttribute(tgemm3, cudaFuncAttributeMaxDynamicSharedMemorySize,
                         TG_SMEM_BYTES);
    tgemm3<<<dim3(4, 128, 3), 256, TG_SMEM_BYTES>>>(                 // 3
        qr, kr, vr, wk, wk, wv, bk, bk, bv, qh, kh, vh, /*roundMask=*/0b110);

    transpose_v<<<dim3(16, 16, BB), 256>>>(vh, vt);                  // 4

    cudaFuncSetAttribute(attn11_kernel, cudaFuncAttributeMaxDynamicSharedMemorySize,
                         ATTN11_SMEM_BYTES);
    attn11_kernel<<<dim3(8, HH, BB), ATH5, ATTN11_SMEM_BYTES>>>(     // 5
        qh, kh, vt, df, gammas, zpad, at);

    tgemm3<<<dim3(4, 128, 1), 256, TG_SMEM_BYTES>>>(                 // 6
        at, at, at, wo, wo, wo, bo, bo, bo, out, out, out, /*roundMask=*/0);
}

// round 15
// speedup vs baseline: 1.0623x; 1.0623x over previous
#include <cuda_runtime.h>
#include <math.h>

#define BB 32
#define SS 512
#define DD 512
#define HH 8
#define DF 64

// ---------------- scratch (no allocation allowed) ----------------
__device__ float g_qh[BB * SS * DD];
__device__ float g_kh[BB * SS * DD];
__device__ float g_vh[BB * SS * DD];
__device__ float g_vt[BB * SS * DD];   // V^T per batch: [b][h*64+d][s]
__device__ float g_at[BB * SS * DD];
__device__ float g_diff[BB * SS * SS];
__device__ float g_qr[BB * SS * DD];
__device__ float g_kr[BB * SS * DD];
__device__ float g_vr[BB * SS * DD];
__device__ float g_wk[DD * DD];
__device__ float g_wv[DD * DD];
__device__ float g_wo[DD * DD];

// ---------------- tf32 helpers ----------------
__device__ __forceinline__ unsigned f2tf(float x) {
    unsigned r;
    asm("cvt.rna.tf32.f32 %0, %1;" : "=r"(r) : "f"(x));
    return r;
}

__device__ __forceinline__ void mma_tf32(float c[4], const unsigned a[4],
                                         unsigned b0, unsigned b1) {
    asm volatile(
        "mma.sync.aligned.m16n8k8.row.col.f32.tf32.tf32.f32 "
        "{%0,%1,%2,%3}, {%4,%5,%6,%7}, {%8,%9}, {%0,%1,%2,%3};\n"
        : "+f"(c[0]), "+f"(c[1]), "+f"(c[2]), "+f"(c[3])
        : "r"(a[0]), "r"(a[1]), "r"(a[2]), "r"(a[3]), "r"(b0), "r"(b1));
}

__device__ __forceinline__ void cp_async16(unsigned smem, const void* g) {
    asm volatile("cp.async.cg.shared.global [%0], [%1], 16;\n" :: "r"(smem), "l"(g));
}

// ---------------- diff precompute (causal triangle only) ----------------
__global__ __launch_bounds__(128) void diff_kernel(const float* __restrict__ qde,
                                                   float* __restrict__ out)
{
    const int i = blockIdx.x, b = blockIdx.y, t = threadIdx.x;
    if (t * 4 > i) return;
    size_t off = ((size_t)b * SS + i) * SS + t * 4;
    float4 x = *(const float4*)(qde + off);
    float4 o;
    o.x = __expf(1.f / (1.f + __expf(-x.x)));
    o.y = __expf(1.f / (1.f + __expf(-x.y)));
    o.z = __expf(1.f / (1.f + __expf(-x.z)));
    o.w = __expf(1.f / (1.f + __expf(-x.w)));
    *(float4*)(out + off) = o;
}

// ---------------- merged tf32 pre-round ----------------
__global__ __launch_bounds__(256) void round_all(
    const float* __restrict__ q, const float* __restrict__ k, const float* __restrict__ v,
    const float* __restrict__ Wk, const float* __restrict__ Wv, const float* __restrict__ Wo,
    float* __restrict__ qr, float* __restrict__ kr, float* __restrict__ vr,
    float* __restrict__ wk, float* __restrict__ wv, float* __restrict__ wo)
{
    const int bx = blockIdx.x;
    const float* s; float* d; int i;
    if (bx < 8192)        { s = q;  d = qr; i = bx * 256 + threadIdx.x; }
    else if (bx < 16384)  { s = k;  d = kr; i = (bx - 8192) * 256 + threadIdx.x; }
    else if (bx < 24576)  { s = v;  d = vr; i = (bx - 16384) * 256 + threadIdx.x; }
    else {
        int w = (bx - 24576) * 256 + threadIdx.x;
        if (w < 65536)       { s = Wk; d = wk; i = w; }
        else if (w < 131072) { s = Wv; d = wv; i = w - 65536; }
        else                 { s = Wo; d = wo; i = w - 131072; }
    }
    float4 x = ((const float4*)s)[i];
    uint4 o = {f2tf(x.x), f2tf(x.y), f2tf(x.z), f2tf(x.w)};
    ((uint4*)d)[i] = o;
}

// ---------------- V transpose: vh [b][s][hd] -> vt [b][hd][s] ----------------
__global__ __launch_bounds__(256) void transpose_v(const float* __restrict__ vh,
                                                   float* __restrict__ vt)
{
    __shared__ float t[32][33];
    const int b = blockIdx.z;
    const int s0 = blockIdx.x * 32, d0 = blockIdx.y * 32;
    const int tx = threadIdx.x & 31, ty = threadIdx.x >> 5;
#pragma unroll
    for (int i = 0; i < 32; i += 8)
        t[ty + i][tx] = vh[((size_t)b * SS + s0 + ty + i) * DD + d0 + tx];
    __syncthreads();
#pragma unroll
    for (int i = 0; i < 32; i += 8)
        vt[((size_t)b * DD + d0 + ty + i) * SS + s0 + tx] = t[tx][ty + i];
}

// ---------------- pipelined tf32 GEMM: C = X @ W^T + bias ----------------
#define TG_SMEM_BYTES 61440
#define NIT 32

__global__ __launch_bounds__(256, 2) void tgemm3(
    const float* __restrict__ X0, const float* __restrict__ X1, const float* __restrict__ X2,
    const float* __restrict__ W0, const float* __restrict__ W1, const float* __restrict__ W2,
    const float* __restrict__ B0, const float* __restrict__ B1, const float* __restrict__ B2,
    float* __restrict__ C0, float* __restrict__ C1, float* __restrict__ C2,
    int roundMask)
{
    extern __shared__ float smem[];
    unsigned* smem_u = (unsigned*)smem;

    const int z = blockIdx.z;
    const float* X = (z == 0) ? X0 : (z == 1) ? X1 : X2;
    const float* W = (z == 0) ? W0 : (z == 1) ? W1 : W2;
    const float* bias = (z == 0) ? B0 : (z == 1) ? B1 : B2;
    float* C = (z == 0) ? C0 : (z == 1) ? C1 : C2;
    const bool rnd = (roundMask >> z) & 1;

    const int tid = threadIdx.x;
    const int lane = tid & 31;
    const int warp = tid >> 5;
    const int m0 = blockIdx.y * 128;
    const int n0 = blockIdx.x * 128;
    const int wm = (warp & 3) * 32;
    const int wn = (warp >> 2) * 64;
    const int g4 = lane >> 2;
    const int t4 = lane & 3;

    float c[2][8][4];
#pragma unroll
    for (int mf = 0; mf < 2; mf++)
#pragma unroll
        for (int nf = 0; nf < 8; nf++)
#pragma unroll
            for (int j = 0; j < 4; j++) c[mf][nf][j] = 0.f;

    const unsigned smem_base = (unsigned)__cvta_generic_to_shared(smem);

#define PREFETCH(st, k0)                                                         \
    {                                                                            \
        const unsigned sb = smem_base + (st) * 5120 * 4;                         \
        _Pragma("unroll")                                                        \
        for (int gch = 0; gch < 2; gch++) {                                      \
            int ch = tid + gch * 256;                                            \
            int row = ch >> 2, c4 = ch & 3;                                      \
            cp_async16(sb + (row * 20 + c4 * 4) * 4,                             \
                       X + (size_t)(m0 + row) * 512 + (k0) + c4 * 4);            \
            cp_async16(sb + (2560 + row * 20 + c4 * 4) * 4,                      \
                       W + (size_t)(n0 + row) * 512 + (k0) + c4 * 4);            \
        }                                                                        \
    }

    PREFETCH(0, 0);
    asm volatile("cp.async.commit_group;\n");
    PREFETCH(1, 16);
    asm volatile("cp.async.commit_group;\n");

    for (int it = 0; it < NIT; it++) {
        asm volatile("cp.async.wait_group 1;\n");
        __syncthreads();

        const int pf = it + 2;
        if (pf < NIT) { PREFETCH(pf % 3, pf * 16); }
        asm volatile("cp.async.commit_group;\n");

        const unsigned* As = smem_u + (it % 3) * 5120;
        const unsigned* Ws = As + 2560;

#pragma unroll
        for (int kk = 0; kk < 16; kk += 8) {
            const int kc = kk + t4;
            unsigned a[2][4], bf[8][2];
#pragma unroll
            for (int mf = 0; mf < 2; mf++) {
                const int ar = wm + mf * 16 + g4;
                a[mf][0] = As[ar * 20 + kc];
                a[mf][1] = As[(ar + 8) * 20 + kc];
                a[mf][2] = As[ar * 20 + kc + 4];
                a[mf][3] = As[(ar + 8) * 20 + kc + 4];
            }
#pragma unroll
            for (int nf = 0; nf < 8; nf++) {
                const int br = wn + nf * 8 + g4;
                bf[nf][0] = Ws[br * 20 + kc];
                bf[nf][1] = Ws[br * 20 + kc + 4];
            }
#pragma unroll
            for (int mf = 0; mf < 2; mf++)
#pragma unroll
                for (int nf = 0; nf < 8; nf++)
                    mma_tf32(c[mf][nf], a[mf], bf[nf][0], bf[nf][1]);
        }
        __syncthreads();
    }

#pragma unroll
    for (int mf = 0; mf < 2; mf++) {
#pragma unroll
        for (int nf = 0; nf < 8; nf++) {
            const int row = m0 + wm + mf * 16 + g4;
            const int col = n0 + wn + nf * 8 + t4 * 2;
            const float b0v = bias[col], b1v = bias[col + 1];
            float v00 = c[mf][nf][0] + b0v, v01 = c[mf][nf][1] + b1v;
            float v10 = c[mf][nf][2] + b0v, v11 = c[mf][nf][3] + b1v;
            if (rnd) {
                v00 = __uint_as_float(f2tf(v00)); v01 = __uint_as_float(f2tf(v01));
                v10 = __uint_as_float(f2tf(v10)); v11 = __uint_as_float(f2tf(v11));
            }
            float2 o0 = {v00, v01}, o1 = {v10, v11};
            *(float2*)(C + (size_t)row * 512 + col) = o0;
            *(float2*)(C + (size_t)(row + 8) * 512 + col) = o1;
        }
    }
}

// ---------------- fused AKT attention v12 (R13 pipeline, single-tf32 Q) ----------------
// SMEM words: stage buf1 0..4352 (qhi during phase 0) | stage buf0 4352..8704 |
//             probs buf 8704..25216 | inv2 25216..25248
#define ATH4 256
#define BSTR 516
#define ATTN12_SMEM_BYTES (25248 * 4)

__global__ __launch_bounds__(256, 2) void attn12_kernel(
    const float* __restrict__ qh, const float* __restrict__ kh,
    const float* __restrict__ vt, const float* __restrict__ diffm,
    const float* __restrict__ gammas, const int* __restrict__ zp,
    float* __restrict__ attn)
{
    extern __shared__ float sm[];
    unsigned* qhi_u = (unsigned*)sm;          // 0..2176 (dead after a-frag load)
    unsigned* buf1_u = (unsigned*)sm;         // staging reuses same region
    unsigned* buf0_u = (unsigned*)(sm + 4352);
    float* buf   = sm + 8704;
    float* inv2  = sm + 25216;
    unsigned* buf_u = (unsigned*)buf;

    const int tid = threadIdx.x;
    const int lane = tid & 31, warp = tid >> 5;
    const int b = blockIdx.z, h = blockIdx.y;
    const int i0 = blockIdx.x * 32;
    const int kmax_pad = min(SS, ((i0 + 32 + 63) >> 6) << 6);
    const int nchunk = kmax_pad >> 6;

    const unsigned* khb_u = (const unsigned*)(kh + (size_t)b * SS * DD + h * DF);
    const float*    qhb   = qh + (size_t)b * SS * DD + h * DF;
    const unsigned* vtb_u = (const unsigned*)(vt + ((size_t)b * DD + h * DF) * SS);
    const float*    dfb   = diffm + (size_t)b * SS * SS;

    const unsigned smem_b = (unsigned)__cvta_generic_to_shared(sm);

#define STAGE_K(kc, dstw)                                                        \
    {                                                                            \
        _Pragma("unroll")                                                        \
        for (int gg = 0; gg < 4; gg++) {                                         \
            int li = tid + gg * 256;                                             \
            int kr = li >> 4, d4 = (li & 15) << 2;                               \
            cp_async16(smem_b + ((dstw) + kr * 68 + d4) * 4,                     \
                       khb_u + (size_t)((kc) * 64 + kr) * DD + d4);              \
        }                                                                        \
    }
#define STAGE_V(kc, dstw)                                                        \
    {                                                                            \
        _Pragma("unroll")                                                        \
        for (int gg = 0; gg < 4; gg++) {                                         \
            int li = tid + gg * 256;                                             \
            int dd = li >> 4, k4 = (li & 15) << 2;                               \
            cp_async16(smem_b + ((dstw) + dd * 68 + k4) * 4,                     \
                       vtb_u + (size_t)dd * SS + (kc) * 64 + k4);                \
        }                                                                        \
    }

    // prefetch K chunk 0 into buf0 immediately (hidden under phase 0)
    STAGE_K(0, 4352u);
    asm volatile("cp.async.commit_group;\n");

    const float g = gammas[h];
    const float gamma_h = -(fmaxf(g, 0.f) + log1pf(__expf(-fabsf(g))));
    const int zpv = zp[0];

    const int g4 = lane >> 2, t4 = lane & 3;
    const int mh = warp & 1;
    const int ng = warp >> 1;
    const int arow = mh * 16 + g4;

    // ---- phase 0: load Q, scale 0.125, round tf32 ----
#pragma unroll
    for (int gg = 0; gg < 2; gg++) {
        int li = tid + gg * 256;
        int r = li >> 4, d4 = (li & 15) << 2;
        float4 v = *(const float4*)(qhb + (size_t)(i0 + r) * DD + d4);
        uint4 hv;
        hv.x = f2tf(v.x * 0.125f);
        hv.y = f2tf(v.y * 0.125f);
        hv.z = f2tf(v.z * 0.125f);
        hv.w = f2tf(v.w * 0.125f);
        *(uint4*)(qhi_u + r * 68 + d4) = hv;
    }
    __syncthreads();

    unsigned ahi[8][4];
#pragma unroll
    for (int ks = 0; ks < 8; ks++) {
        int base = arow * 68 + ks * 8 + t4;
        ahi[ks][0] = qhi_u[base];
        ahi[ks][1] = qhi_u[base + 8 * 68];
        ahi[ks][2] = qhi_u[base + 4];
        ahi[ks][3] = qhi_u[base + 8 * 68 + 4];
    }
    __syncthreads();   // a-frags read; buf1 region free for staging

    if (nchunk > 1) STAGE_K(1, 0u);
    asm volatile("cp.async.commit_group;\n");

    // ---- phase 1: S = (Q/8) K^T, double-buffered ----
    for (int kc = 0; kc < nchunk; kc++) {
        asm volatile("cp.async.wait_group 1;\n");
        __syncthreads();
        const unsigned* st = (kc & 1) ? buf1_u : buf0_u;

#pragma unroll
        for (int sub = 0; sub < 2; sub++) {
            const int nt = 2 * ng + sub;
            if (kc * 64 + nt * 8 <= i0 + 31) {
                float c[4] = {0.f, 0.f, 0.f, 0.f};
#pragma unroll
                for (int ks = 0; ks < 8; ks++) {
                    unsigned b0 = st[(nt * 8 + g4) * 68 + ks * 8 + t4];
                    unsigned b1 = st[(nt * 8 + g4) * 68 + ks * 8 + t4 + 4];
                    mma_tf32(c, ahi[ks], b0, b1);
                }
                const int col = kc * 64 + nt * 8 + t4 * 2;
                float2 v0 = {c[0], c[1]}, v1 = {c[2], c[3]};
                *(float2*)(buf + arow * BSTR + col) = v0;
                *(float2*)(buf + (arow + 8) * BSTR + col) = v1;
            }
        }
        __syncthreads();

        const int pf = kc + 2;
        if (pf < nchunk) {
            if (pf & 1) { STAGE_K(pf, 0u); } else { STAGE_K(pf, 4352u); }
        }
        asm volatile("cp.async.commit_group;\n");
    }

    // prefetch V chunks 0 and 1 — land during phase 2
    STAGE_V(0, 4352u);
    asm volatile("cp.async.commit_group;\n");
    if (nchunk > 1) STAGE_V(1, 0u);
    asm volatile("cp.async.commit_group;\n");

    // ---- phase 2: softmax1 -> cumsum -> decay -> softmax2 ----
    for (int rr = 0; rr < 4; rr++) {
        const int r = warp + rr * 8;
        const int i = i0 + r;
        float* row = buf + r * BSTR;
        unsigned* row_u = buf_u + r * BSTR;
        const float* drow = dfb + (size_t)i * SS;
        const int kb = lane * 16;
        const bool act = kb < kmax_pad;

        float s[16], dfv[16];
        if (act) {
#pragma unroll
            for (int j4 = 0; j4 < 4; j4++) {
                float4 v = *(float4*)(row + kb + j4 * 4);
                s[j4 * 4 + 0] = v.x; s[j4 * 4 + 1] = v.y;
                s[j4 * 4 + 2] = v.z; s[j4 * 4 + 3] = v.w;
                float4 dv = *(const float4*)(drow + kb + j4 * 4);
                dfv[j4 * 4 + 0] = dv.x; dfv[j4 * 4 + 1] = dv.y;
                dfv[j4 * 4 + 2] = dv.z; dfv[j4 * 4 + 3] = dv.w;
            }
        }

        float m1 = -1e32f;
#pragma unroll
        for (int j = 0; j < 16; j++)
            if (act && kb + j <= i) m1 = fmaxf(m1, s[j]);
#pragma unroll
        for (int o = 16; o > 0; o >>= 1) m1 = fmaxf(m1, __shfl_xor_sync(0xffffffffu, m1, o));

        float e[16];
        float run = 0.f;
#pragma unroll
        for (int j = 0; j < 16; j++) {
            e[j] = (act && kb + j <= i) ? __expf(s[j] - m1) : 0.f;
            run += e[j];
        }
        float tsc = run;
#pragma unroll
        for (int o = 1; o < 32; o <<= 1) {
            float u = __shfl_up_sync(0xffffffffu, tsc, o);
            if (lane >= o) tsc += u;
        }
        const float sum1 = __shfl_sync(0xffffffffu, tsc, 31);
        float cdf = tsc - run;
        const float invs = 1.f / sum1;

        float m2 = -1e32f;
#pragma unroll
        for (int j = 0; j < 16; j++) {
            cdf += e[j];
            const int k = kb + j;
            if (act && k <= i) {
                float rem = (sum1 - cdf) * invs;
                float px = rem * (float)(i - k);
                float dist = (px > 1e-30f) ? px * rsqrtf(px) : 0.f;
                float te = __expf(dist * gamma_h * dfv[j]);
                te = fminf(fmaxf(te, 1e-5f), 1e5f);
                float s2 = s[j] * te;
                s[j] = s2;
                m2 = fmaxf(m2, s2);
            } else {
                s[j] = -1e32f;
            }
        }
#pragma unroll
        for (int o = 16; o > 0; o >>= 1) m2 = fmaxf(m2, __shfl_xor_sync(0xffffffffu, m2, o));

        float sum2 = 0.f;
#pragma unroll
        for (int j = 0; j < 16; j++) {
            float e2 = (act && kb + j <= i) ? __expf(s[j] - m2) : 0.f;
            sum2 += e2;
            s[j] = e2;
        }
#pragma unroll
        for (int o = 16; o > 0; o >>= 1) sum2 += __shfl_xor_sync(0xffffffffu, sum2, o);

        if (act) {
#pragma unroll
            for (int j4 = 0; j4 < 4; j4++) {
                uint4 v;
                v.x = f2tf(s[j4 * 4 + 0]); v.y = f2tf(s[j4 * 4 + 1]);
                v.z = f2tf(s[j4 * 4 + 2]); v.w = f2tf(s[j4 * 4 + 3]);
                *(uint4*)(row_u + kb + j4 * 4) = v;
            }
        }
        if (lane == 0) inv2[r] = (i == 0 && zpv) ? 0.f : 1.f / sum2;
    }
    __syncthreads();

    // ---- phase 3: O = P V, double-buffered V^T ----
    {
        float co[2][4];
#pragma unroll
        for (int sub = 0; sub < 2; sub++)
#pragma unroll
            for (int j = 0; j < 4; j++) co[sub][j] = 0.f;

        for (int kc = 0; kc < nchunk; kc++) {
            asm volatile("cp.async.wait_group 1;\n");
            __syncthreads();
            const unsigned* st = (kc & 1) ? buf1_u : buf0_u;

#pragma unroll
            for (int ks = 0; ks < 8; ks++) {
                const int ki = kc * 64 + ks * 8 + t4;
                unsigned a[4];
                a[0] = buf_u[arow * BSTR + ki];
                a[1] = buf_u[(arow + 8) * BSTR + ki];
                a[2] = buf_u[arow * BSTR + ki + 4];
                a[3] = buf_u[(arow + 8) * BSTR + ki + 4];
#pragma unroll
                for (int sub = 0; sub < 2; sub++) {
                    const int nt = 2 * ng + sub;
                    unsigned b0 = st[(nt * 8 + g4) * 68 + ks * 8 + t4];
                    unsigned b1 = st[(nt * 8 + g4) * 68 + ks * 8 + t4 + 4];
                    mma_tf32(co[sub], a, b0, b1);
                }
            }
            __syncthreads();

            const int pf = kc + 2;
            if (pf < nchunk) {
                if (pf & 1) { STAGE_V(pf, 0u); } else { STAGE_V(pf, 4352u); }
            }
            asm volatile("cp.async.commit_group;\n");
        }

        const float s0 = inv2[arow];
        const float s1 = inv2[arow + 8];
#pragma unroll
        for (int sub = 0; sub < 2; sub++) {
            const int nt = 2 * ng + sub;
            const int col = h * DF + nt * 8 + t4 * 2;
            float2 o0, o1;
            o0.x = __uint_as_float(f2tf(co[sub][0] * s0));
            o0.y = __uint_as_float(f2tf(co[sub][1] * s0));
            o1.x = __uint_as_float(f2tf(co[sub][2] * s1));
            o1.y = __uint_as_float(f2tf(co[sub][3] * s1));
            *(float2*)(attn + ((size_t)b * SS + i0 + arow) * DD + col) = o0;
            *(float2*)(attn + ((size_t)b * SS + i0 + arow + 8) * DD + col) = o1;
        }
    }
#undef STAGE_K
#undef STAGE_V
}

// ---------------- launch ----------------
extern "C" void kernel_launch(void* const* d_in, const int* in_sizes, int n_in,
                              void* d_out, int out_size)
{
    const float* q      = (const float*)d_in[0];
    const float* k      = (const float*)d_in[1];
    const float* v      = (const float*)d_in[2];
    const int*   zpad   = (const int*)d_in[4];
    const float* qde    = (const float*)d_in[5];
    const float* Wk     = (const float*)d_in[6];
    const float* bk     = (const float*)d_in[7];
    const float* Wv     = (const float*)d_in[8];
    const float* bv     = (const float*)d_in[9];
    const float* Wo     = (const float*)d_in[10];
    const float* bo     = (const float*)d_in[11];
    const float* gammas = (const float*)d_in[12];
    float* out = (float*)d_out;

    float *qh, *kh, *vh, *vt, *at, *df, *qr, *kr, *vr, *wk, *wv, *wo;
    cudaGetSymbolAddress((void**)&qh, g_qh);
    cudaGetSymbolAddress((void**)&kh, g_kh);
    cudaGetSymbolAddress((void**)&vh, g_vh);
    cudaGetSymbolAddress((void**)&vt, g_vt);
    cudaGetSymbolAddress((void**)&at, g_at);
    cudaGetSymbolAddress((void**)&df, g_diff);
    cudaGetSymbolAddress((void**)&qr, g_qr);
    cudaGetSymbolAddress((void**)&kr, g_kr);
    cudaGetSymbolAddress((void**)&vr, g_vr);
    cudaGetSymbolAddress((void**)&wk, g_wk);
    cudaGetSymbolAddress((void**)&wv, g_wv);
    cudaGetSymbolAddress((void**)&wo, g_wo);

    diff_kernel<<<dim3(SS, BB), 128>>>(qde, df);                     // 1
    round_all<<<25344, 256>>>(q, k, v, Wk, Wv, Wo,
                              qr, kr, vr, wk, wv, wo);               // 2

    cudaFuncSetAttribute(tgemm3, cudaFuncAttributeMaxDynamicSharedMemorySize,
                         TG_SMEM_BYTES);
    tgemm3<<<dim3(4, 128, 3), 256, TG_SMEM_BYTES>>>(                 // 3
        qr, kr, vr, wk, wk, wv, bk, bk, bv, qh, kh, vh, /*roundMask=*/0b110);

    transpose_v<<<dim3(16, 16, BB), 256>>>(vh, vt);                  // 4

    cudaFuncSetAttribute(attn12_kernel, cudaFuncAttributeMaxDynamicSharedMemorySize,
                         ATTN12_SMEM_BYTES);
    attn12_kernel<<<dim3(16, HH, BB), ATH4, ATTN12_SMEM_BYTES>>>(    // 5
        qh, kh, vt, df, gammas, zpad, at);

    tgemm3<<<dim3(4, 128, 1), 256, TG_SMEM_BYTES>>>(                 // 6
        at, at, at, wo, wo, wo, bo, bo, bo, out, out, out, /*roundMask=*/0);
}